// round 10
// baseline (speedup 1.0000x reference)
#include <cuda_runtime.h>
#include <cuda_fp16.h>

#define D 256
#define H1 128
#define H2 64
#define N_NODES_MAX 100000

// Folded weights: g_w[0..255] = class-0 column of W1@W2@W3, g_w[256..511] = class 1.
__device__ float g_w[2 * D];
__device__ float g_b[2];
// fp16 copy of h: one row = 256 halves = 512 B = 32 uint4. 51.2 MB scratch.
__device__ uint4 g_h16[N_NODES_MAX * (D / 8)];

// Packed fp32x2 ops (sm_103a): 2 fp32 FMAs per instruction.
#define FMA_F32X2(d, a, b, c) \
    asm("fma.rn.f32x2 %0, %1, %2, %3;" : "=l"(d) : "l"(a), "l"(b), "l"(c))
#define PACK_F32X2(out, lo, hi) \
    asm("mov.b64 %0, {%1, %2};" : "=l"(out) : "f"(lo), "f"(hi))
#define UNPACK_F32X2(lo, hi, in) \
    asm("mov.b64 {%0, %1}, %2;" : "=f"(lo), "=f"(hi) : "l"(in))

// ---------------------------------------------------------------------------
// Prep kernel (one launch):
//   blocks [0, convBlocks)          : convert h (fp32) -> g_h16 (fp16)
//   blocks [convBlocks, +32)        : fold W_eff = W1@(W2@W3), b_eff (fp32)
// The two halves touch disjoint data; safe to run concurrently.
// ---------------------------------------------------------------------------
__global__ void __launch_bounds__(256)
prep_kernel(const float* __restrict__ h, int nElems, int convBlocks,
            const float* __restrict__ W1, const float* __restrict__ W2,
            const float* __restrict__ W3, const float* __restrict__ b1,
            const float* __restrict__ b2, const float* __restrict__ b3) {
    if (blockIdx.x < (unsigned)convBlocks) {
        // ---- fp32 -> fp16 conversion: 8 elements per thread ----
        const int idx  = blockIdx.x * 256 + threadIdx.x;
        const int base = idx * 8;
        if (base < nElems) {
            const float4* src = (const float4*)h + idx * 2;
            const float4 f0 = __ldg(src);
            const float4 f1 = __ldg(src + 1);
            __half2 hh[4];
            hh[0] = __floats2half2_rn(f0.x, f0.y);
            hh[1] = __floats2half2_rn(f0.z, f0.w);
            hh[2] = __floats2half2_rn(f1.x, f1.y);
            hh[3] = __floats2half2_rn(f1.z, f1.w);
            g_h16[idx] = *(const uint4*)hh;
        }
        return;
    }

    // ---- Fold: 32 blocks, each computes W23 in smem + 8 W_eff rows ----
    const int fb   = blockIdx.x - convBlocks;   // 0..31
    const int tid  = threadIdx.x;
    const int warp = tid >> 5;                  // 0..7
    const int lane = tid & 31;

    __shared__ float sW23c0[H1];
    __shared__ float sW23c1[H1];
    __shared__ float sTvec[H2];

    {   // W23 entry (k = tid>>1, c = tid&1): length-64 dot
        const int k = tid >> 1;
        const int c = tid & 1;
        const float* w2row = &W2[k * H2];
        float acc = 0.0f;
#pragma unroll 16
        for (int j = 0; j < H2; ++j)
            acc = fmaf(w2row[j], W3[j * 2 + c], acc);
        if (c == 0) sW23c0[k] = acc;
        else        sW23c1[k] = acc;
    }
    __syncthreads();

    {   // W_eff row 8*fb + warp
        const int row = fb * 8 + warp;          // 0..255
        const float4 a  = *(const float4*)&W1[row * H1 + 4 * lane];
        const float4 c0 = *(const float4*)&sW23c0[4 * lane];
        const float4 c1 = *(const float4*)&sW23c1[4 * lane];

        float s0, s1;
        s0 = a.x * c0.x;            s1 = a.x * c1.x;
        s0 = fmaf(a.y, c0.y, s0);   s1 = fmaf(a.y, c1.y, s1);
        s0 = fmaf(a.z, c0.z, s0);   s1 = fmaf(a.z, c1.z, s1);
        s0 = fmaf(a.w, c0.w, s0);   s1 = fmaf(a.w, c1.w, s1);
#pragma unroll
        for (int o = 16; o > 0; o >>= 1) {
            s0 += __shfl_xor_sync(0xffffffffu, s0, o);
            s1 += __shfl_xor_sync(0xffffffffu, s1, o);
        }
        if (lane == 0) {
            g_w[row]     = s0;
            g_w[D + row] = s1;
        }
    }

    if (fb == 0) {   // bias chain
#pragma unroll
        for (int jj = 0; jj < 8; ++jj) {
            const int j = warp * 8 + jj;
            float v =      b1[lane]      * W2[(lane)      * H2 + j];
            v = fmaf(b1[lane + 32],  W2[(lane + 32) * H2 + j], v);
            v = fmaf(b1[lane + 64],  W2[(lane + 64) * H2 + j], v);
            v = fmaf(b1[lane + 96],  W2[(lane + 96) * H2 + j], v);
#pragma unroll
            for (int o = 16; o > 0; o >>= 1)
                v += __shfl_xor_sync(0xffffffffu, v, o);
            if (lane == 0) sTvec[j] = v + b2[j];
        }
        __syncthreads();
        if (warp == 0) {
            float t0 = sTvec[lane], t1 = sTvec[lane + 32];
            float bb0 = fmaf(t0, W3[lane * 2 + 0], t1 * W3[(lane + 32) * 2 + 0]);
            float bb1 = fmaf(t0, W3[lane * 2 + 1], t1 * W3[(lane + 32) * 2 + 1]);
#pragma unroll
            for (int o = 16; o > 0; o >>= 1) {
                bb0 += __shfl_xor_sync(0xffffffffu, bb0, o);
                bb1 += __shfl_xor_sync(0xffffffffu, bb1, o);
            }
            if (lane == 0) {
                g_b[0] = bb0 + b3[0];
                g_b[1] = bb1 + b3[1];
            }
        }
    }
}

// ---------------------------------------------------------------------------
// Main kernel: one warp per edge, grid-stride; fp16 gathers (512 B/row).
// Lane l owns channels [8l..8l+7]: one uint4 load per row per lane.
// Hadamard in half2 (HMUL2), accumulate in packed fp32 (FFMA2).
// ---------------------------------------------------------------------------
__global__ void __launch_bounds__(256)
edge_predict_fp16(const int* __restrict__ edges,
                  float* __restrict__ out, int E) {
    const int lane   = threadIdx.x & 31;
    const int warp   = (blockIdx.x * blockDim.x + threadIdx.x) >> 5;
    const int nwarps = (gridDim.x * blockDim.x) >> 5;

    // Per-lane weights packed as f32x2 pairs: channel pair (2k, 2k+1).
    unsigned long long w0p[4], w1p[4];
#pragma unroll
    for (int k = 0; k < 4; ++k) {
        PACK_F32X2(w0p[k], g_w[8 * lane + 2 * k],     g_w[8 * lane + 2 * k + 1]);
        PACK_F32X2(w1p[k], g_w[D + 8 * lane + 2 * k], g_w[D + 8 * lane + 2 * k + 1]);
    }
    const float bias0 = g_b[0];
    const float bias1 = g_b[1];

    for (int e = warp; e < E; e += nwarps) {
        const int2 st = __ldg((const int2*)edges + e);

        const uint4* hs = g_h16 + (size_t)st.x * (D / 8);
        const uint4* ht = g_h16 + (size_t)st.y * (D / 8);
        const uint4 xv = __ldg(hs + lane);
        const uint4 yv = __ldg(ht + lane);

        const __half2* xh = (const __half2*)&xv;
        const __half2* yh = (const __half2*)&yv;

        unsigned long long acc0 = 0ull, acc1 = 0ull;   // (0.0f, 0.0f)
#pragma unroll
        for (int k = 0; k < 4; ++k) {
            const __half2 p  = __hmul2(xh[k], yh[k]);   // hadamard, fp16
            const float2  pf = __half22float2(p);       // to fp32
            unsigned long long pp;
            PACK_F32X2(pp, pf.x, pf.y);
            FMA_F32X2(acc0, pp, w0p[k], acc0);          // 2 fp32 FMAs/instr
            FMA_F32X2(acc1, pp, w1p[k], acc1);
        }
        float a0l, a0h, a1l, a1h;
        UNPACK_F32X2(a0l, a0h, acc0);
        UNPACK_F32X2(a1l, a1h, acc1);
        float a0 = a0l + a0h;
        float a1 = a1l + a1h;

#pragma unroll
        for (int o = 16; o > 0; o >>= 1) {
            a0 += __shfl_xor_sync(0xffffffffu, a0, o);
            a1 += __shfl_xor_sync(0xffffffffu, a1, o);
        }

        if (lane == 0) {
            a0 += bias0;
            a1 += bias1;
            float m  = fmaxf(a0, a1);
            float e0 = expf(a0 - m);
            float e1 = expf(a1 - m);
            float inv = 1.0f / (e0 + e1);
            ((float2*)out)[e] = make_float2(e0 * inv, e1 * inv);
        }
    }
}

extern "C" void kernel_launch(void* const* d_in, const int* in_sizes, int n_in,
                              void* d_out, int out_size) {
    const float* h     = (const float*)d_in[0];
    const int*   edges = (const int*)d_in[1];
    const float* W1    = (const float*)d_in[2];
    const float* b1    = (const float*)d_in[3];
    const float* W2    = (const float*)d_in[4];
    const float* b2    = (const float*)d_in[5];
    const float* W3    = (const float*)d_in[6];
    const float* b3    = (const float*)d_in[7];
    float*       out   = (float*)d_out;

    const int nElems = in_sizes[0];          // 25.6M floats of h
    const int E      = in_sizes[1] / 2;

    const int convBlocks = (nElems / 8 + 255) / 256;   // 12500
    prep_kernel<<<convBlocks + 32, 256>>>(h, nElems, convBlocks,
                                          W1, W2, W3, b1, b2, b3);
    // 8880 = 148 x 60: integer number of waves at 5 or 6 resident CTAs/SM.
    edge_predict_fp16<<<8880, 256>>>(edges, out, E);
}

// round 11
// speedup vs baseline: 1.2163x; 1.2163x over previous
#include <cuda_runtime.h>
#include <cuda_fp16.h>

#define D 256
#define H1 128
#define H2 64
#define N_NODES_MAX 100000

// Folded weights: g_w[0..255] = class-0 column of W1@W2@W3, g_w[256..511] = class 1.
__device__ float g_w[2 * D];
__device__ float g_b[2];
// fp16 copy of h: one row = 256 halves = 512 B = 32 uint4. 51.2 MB scratch.
__device__ uint4 g_h16[N_NODES_MAX * (D / 8)];

// Packed fp32x2 ops (sm_103a): 2 fp32 FMAs per instruction.
#define FMA_F32X2(d, a, b, c) \
    asm("fma.rn.f32x2 %0, %1, %2, %3;" : "=l"(d) : "l"(a), "l"(b), "l"(c))
#define PACK_F32X2(out, lo, hi) \
    asm("mov.b64 %0, {%1, %2};" : "=l"(out) : "f"(lo), "f"(hi))
#define UNPACK_F32X2(lo, hi, in) \
    asm("mov.b64 {%0, %1}, %2;" : "=f"(lo), "=f"(hi) : "l"(in))

// ---------------------------------------------------------------------------
// Prep kernel (one launch):
//   blocks [0, convBlocks) : convert h (fp32) -> g_h16 (fp16)   [DRAM-floor]
//   blocks [convBlocks,+32): fold W_eff = W1@(W2@W3), b_eff     (fp32)
// ---------------------------------------------------------------------------
__global__ void __launch_bounds__(256)
prep_kernel(const float* __restrict__ h, int nElems, int convBlocks,
            const float* __restrict__ W1, const float* __restrict__ W2,
            const float* __restrict__ W3, const float* __restrict__ b1,
            const float* __restrict__ b2, const float* __restrict__ b3) {
    if (blockIdx.x < (unsigned)convBlocks) {
        const int idx  = blockIdx.x * 256 + threadIdx.x;
        const int base = idx * 8;
        if (base < nElems) {
            const float4* src = (const float4*)h + idx * 2;
            const float4 f0 = __ldg(src);
            const float4 f1 = __ldg(src + 1);
            __half2 hh[4];
            hh[0] = __floats2half2_rn(f0.x, f0.y);
            hh[1] = __floats2half2_rn(f0.z, f0.w);
            hh[2] = __floats2half2_rn(f1.x, f1.y);
            hh[3] = __floats2half2_rn(f1.z, f1.w);
            g_h16[idx] = *(const uint4*)hh;
        }
        return;
    }

    const int fb   = blockIdx.x - convBlocks;   // 0..31
    const int tid  = threadIdx.x;
    const int warp = tid >> 5;                  // 0..7
    const int lane = tid & 31;

    __shared__ float sW23c0[H1];
    __shared__ float sW23c1[H1];
    __shared__ float sTvec[H2];

    {   // W23 entry (k = tid>>1, c = tid&1): length-64 dot
        const int k = tid >> 1;
        const int c = tid & 1;
        const float* w2row = &W2[k * H2];
        float acc = 0.0f;
#pragma unroll 16
        for (int j = 0; j < H2; ++j)
            acc = fmaf(w2row[j], W3[j * 2 + c], acc);
        if (c == 0) sW23c0[k] = acc;
        else        sW23c1[k] = acc;
    }
    __syncthreads();

    {   // W_eff row 8*fb + warp
        const int row = fb * 8 + warp;
        const float4 a  = *(const float4*)&W1[row * H1 + 4 * lane];
        const float4 c0 = *(const float4*)&sW23c0[4 * lane];
        const float4 c1 = *(const float4*)&sW23c1[4 * lane];

        float s0, s1;
        s0 = a.x * c0.x;            s1 = a.x * c1.x;
        s0 = fmaf(a.y, c0.y, s0);   s1 = fmaf(a.y, c1.y, s1);
        s0 = fmaf(a.z, c0.z, s0);   s1 = fmaf(a.z, c1.z, s1);
        s0 = fmaf(a.w, c0.w, s0);   s1 = fmaf(a.w, c1.w, s1);
#pragma unroll
        for (int o = 16; o > 0; o >>= 1) {
            s0 += __shfl_xor_sync(0xffffffffu, s0, o);
            s1 += __shfl_xor_sync(0xffffffffu, s1, o);
        }
        if (lane == 0) {
            g_w[row]     = s0;
            g_w[D + row] = s1;
        }
    }

    if (fb == 0) {   // bias chain
#pragma unroll
        for (int jj = 0; jj < 8; ++jj) {
            const int j = warp * 8 + jj;
            float v =      b1[lane]      * W2[(lane)      * H2 + j];
            v = fmaf(b1[lane + 32],  W2[(lane + 32) * H2 + j], v);
            v = fmaf(b1[lane + 64],  W2[(lane + 64) * H2 + j], v);
            v = fmaf(b1[lane + 96],  W2[(lane + 96) * H2 + j], v);
#pragma unroll
            for (int o = 16; o > 0; o >>= 1)
                v += __shfl_xor_sync(0xffffffffu, v, o);
            if (lane == 0) sTvec[j] = v + b2[j];
        }
        __syncthreads();
        if (warp == 0) {
            float t0 = sTvec[lane], t1 = sTvec[lane + 32];
            float bb0 = fmaf(t0, W3[lane * 2 + 0], t1 * W3[(lane + 32) * 2 + 0]);
            float bb1 = fmaf(t0, W3[lane * 2 + 1], t1 * W3[(lane + 32) * 2 + 1]);
#pragma unroll
            for (int o = 16; o > 0; o >>= 1) {
                bb0 += __shfl_xor_sync(0xffffffffu, bb0, o);
                bb1 += __shfl_xor_sync(0xffffffffu, bb1, o);
            }
            if (lane == 0) {
                g_b[0] = bb0 + b3[0];
                g_b[1] = bb1 + b3[1];
            }
        }
    }
}

// ---------------------------------------------------------------------------
// Main kernel: TWO edges per warp-iteration (int4 edge load, 8 gathers in
// flight), 32-bit byte-offset addressing into the 51.2 MB fp16 table, and a
// 4-way split butterfly that reduces all four logits in 7 shfl + 7 add.
// Lane 0 finalizes edge0's softmax; lane 16 finalizes edge1's.
// ---------------------------------------------------------------------------
__global__ void __launch_bounds__(256)
edge_predict_fp16(const int* __restrict__ edges,
                  float* __restrict__ out, int E) {
    const int  lane   = threadIdx.x & 31;
    const int  warp   = (blockIdx.x * blockDim.x + threadIdx.x) >> 5;
    const int  nwarps = (gridDim.x * blockDim.x) >> 5;
    const int  nPairs = E >> 1;                       // E is even (1M)
    const char* tbl   = (const char*)g_h16;
    const unsigned laneOff = (unsigned)lane << 4;     // 16 B per lane

    // Per-lane weights packed as f32x2 pairs for channels 8l..8l+7.
    unsigned long long w0p[4], w1p[4];
#pragma unroll
    for (int k = 0; k < 4; ++k) {
        PACK_F32X2(w0p[k], g_w[8 * lane + 2 * k],     g_w[8 * lane + 2 * k + 1]);
        PACK_F32X2(w1p[k], g_w[D + 8 * lane + 2 * k], g_w[D + 8 * lane + 2 * k + 1]);
    }
    const float bias0 = g_b[0];
    const float bias1 = g_b[1];
    const bool  hi16  = (lane & 16) != 0;
    const bool  hi8   = (lane & 8) != 0;

    for (int p = warp; p < nPairs; p += nwarps) {
        const int4 q = __ldg((const int4*)edges + p);   // edges 2p and 2p+1

        // 32-bit byte offsets: idx*512 + lane*16 (table < 4 GB).
        const uint4 x0 = __ldg((const uint4*)(tbl + (((unsigned)q.x << 9) + laneOff)));
        const uint4 y0 = __ldg((const uint4*)(tbl + (((unsigned)q.y << 9) + laneOff)));
        const uint4 x1 = __ldg((const uint4*)(tbl + (((unsigned)q.z << 9) + laneOff)));
        const uint4 y1 = __ldg((const uint4*)(tbl + (((unsigned)q.w << 9) + laneOff)));

        const __half2* xh0 = (const __half2*)&x0;
        const __half2* yh0 = (const __half2*)&y0;
        const __half2* xh1 = (const __half2*)&x1;
        const __half2* yh1 = (const __half2*)&y1;

        unsigned long long A = 0ull, B = 0ull, C = 0ull, Dv = 0ull;
#pragma unroll
        for (int k = 0; k < 4; ++k) {
            const float2 p0 = __half22float2(__hmul2(xh0[k], yh0[k]));
            const float2 p1 = __half22float2(__hmul2(xh1[k], yh1[k]));
            unsigned long long pp0, pp1;
            PACK_F32X2(pp0, p0.x, p0.y);
            PACK_F32X2(pp1, p1.x, p1.y);
            FMA_F32X2(A,  pp0, w0p[k], A);    // edge0 class0
            FMA_F32X2(B,  pp0, w1p[k], B);    // edge0 class1
            FMA_F32X2(C,  pp1, w0p[k], C);    // edge1 class0
            FMA_F32X2(Dv, pp1, w1p[k], Dv);   // edge1 class1
        }
        float al, ah, a, b, c, d;
        UNPACK_F32X2(al, ah, A);  a = al + ah;
        UNPACK_F32X2(al, ah, B);  b = al + ah;
        UNPACK_F32X2(al, ah, C);  c = al + ah;
        UNPACK_F32X2(al, ah, Dv); d = al + ah;

        // 4-way split reduction.
        // xor16: low half accumulates edge0 {a,b}, high half edge1 {c,d}.
        float v1 = (hi16 ? c : a) + __shfl_xor_sync(0xffffffffu, hi16 ? a : c, 16);
        float v2 = (hi16 ? d : b) + __shfl_xor_sync(0xffffffffu, hi16 ? b : d, 16);
        // xor8: quarters -> lanes 0-7:e0a0, 8-15:e0a1, 16-23:e1a0, 24-31:e1a1.
        float v = (hi8 ? v2 : v1) + __shfl_xor_sync(0xffffffffu, hi8 ? v1 : v2, 8);
        // shared butterflies within each 8-lane group.
        v += __shfl_xor_sync(0xffffffffu, v, 4);
        v += __shfl_xor_sync(0xffffffffu, v, 2);
        v += __shfl_xor_sync(0xffffffffu, v, 1);
        // lane 0 holds its edge's a0; partner class is 8 lanes away.
        const float vo = __shfl_xor_sync(0xffffffffu, v, 8);

        if ((lane & 15) == 0) {            // lane 0 -> edge 2p, lane 16 -> 2p+1
            const float l0 = v  + bias0;
            const float l1 = vo + bias1;
            const float m  = fmaxf(l0, l1);
            const float e0 = expf(l0 - m);
            const float e1 = expf(l1 - m);
            const float inv = 1.0f / (e0 + e1);
            ((float2*)out)[2 * p + (lane >> 4)] = make_float2(e0 * inv, e1 * inv);
        }
    }

    // Tail for odd E (not hit for E = 1M, kept for safety).
    if ((E & 1) && warp == 0) {
        const int e = E - 1;
        const int2 st = __ldg((const int2*)edges + e);
        const uint4 xv = __ldg((const uint4*)(tbl + (((unsigned)st.x << 9) + laneOff)));
        const uint4 yv = __ldg((const uint4*)(tbl + (((unsigned)st.y << 9) + laneOff)));
        const __half2* xh = (const __half2*)&xv;
        const __half2* yh = (const __half2*)&yv;
        unsigned long long A = 0ull, B = 0ull;
#pragma unroll
        for (int k = 0; k < 4; ++k) {
            const float2 pf = __half22float2(__hmul2(xh[k], yh[k]));
            unsigned long long pp;
            PACK_F32X2(pp, pf.x, pf.y);
            FMA_F32X2(A, pp, w0p[k], A);
            FMA_F32X2(B, pp, w1p[k], B);
        }
        float al, ah;
        UNPACK_F32X2(al, ah, A); float a0 = al + ah;
        UNPACK_F32X2(al, ah, B); float a1 = al + ah;
#pragma unroll
        for (int o = 16; o > 0; o >>= 1) {
            a0 += __shfl_xor_sync(0xffffffffu, a0, o);
            a1 += __shfl_xor_sync(0xffffffffu, a1, o);
        }
        if (lane == 0) {
            a0 += bias0; a1 += bias1;
            const float m  = fmaxf(a0, a1);
            const float e0 = expf(a0 - m);
            const float e1 = expf(a1 - m);
            const float inv = 1.0f / (e0 + e1);
            ((float2*)out)[e] = make_float2(e0 * inv, e1 * inv);
        }
    }
}

extern "C" void kernel_launch(void* const* d_in, const int* in_sizes, int n_in,
                              void* d_out, int out_size) {
    const float* h     = (const float*)d_in[0];
    const int*   edges = (const int*)d_in[1];
    const float* W1    = (const float*)d_in[2];
    const float* b1    = (const float*)d_in[3];
    const float* W2    = (const float*)d_in[4];
    const float* b2    = (const float*)d_in[5];
    const float* W3    = (const float*)d_in[6];
    const float* b3    = (const float*)d_in[7];
    float*       out   = (float*)d_out;

    const int nElems = in_sizes[0];
    const int E      = in_sizes[1] / 2;

    const int convBlocks = (nElems / 8 + 255) / 256;   // 12500
    prep_kernel<<<convBlocks + 32, 256>>>(h, nElems, convBlocks,
                                          W1, W2, W3, b1, b2, b3);
    // 8880 = 148 x 60: integer number of waves at 5 or 6 resident CTAs/SM.
    edge_predict_fp16<<<8880, 256>>>(edges, out, E);
}

// round 12
// speedup vs baseline: 1.2554x; 1.0321x over previous
#include <cuda_runtime.h>
#include <cuda_fp16.h>

#define D 256
#define H1 128
#define H2 64
#define N_NODES_MAX 100000

// Folded weights: g_w[0..255] = class-0 column of W1@W2@W3, g_w[256..511] = class 1.
__device__ float g_w[2 * D];
__device__ float g_b[2];
// fp16 copy of h: one row = 256 halves = 512 B = 32 uint4. 51.2 MB scratch.
__device__ uint4 g_h16[N_NODES_MAX * (D / 8)];

// Packed fp32x2 ops (sm_103a): 2 fp32 FMAs per instruction.
#define FMA_F32X2(d, a, b, c) \
    asm("fma.rn.f32x2 %0, %1, %2, %3;" : "=l"(d) : "l"(a), "l"(b), "l"(c))
#define PACK_F32X2(out, lo, hi) \
    asm("mov.b64 %0, {%1, %2};" : "=l"(out) : "f"(lo), "f"(hi))
#define UNPACK_F32X2(lo, hi, in) \
    asm("mov.b64 {%0, %1}, %2;" : "=f"(lo), "=f"(hi) : "l"(in))

// ---------------------------------------------------------------------------
// Prep kernel (one launch):
//   blocks [0, convBlocks) : convert h (fp32) -> g_h16 (fp16)   [DRAM-floor]
//   blocks [convBlocks,+32): fold W_eff = W1@(W2@W3), b_eff     (fp32)
// ---------------------------------------------------------------------------
__global__ void __launch_bounds__(256)
prep_kernel(const float* __restrict__ h, int nElems, int convBlocks,
            const float* __restrict__ W1, const float* __restrict__ W2,
            const float* __restrict__ W3, const float* __restrict__ b1,
            const float* __restrict__ b2, const float* __restrict__ b3) {
    if (blockIdx.x < (unsigned)convBlocks) {
        const int idx  = blockIdx.x * 256 + threadIdx.x;
        const int base = idx * 8;
        if (base < nElems) {
            const float4* src = (const float4*)h + idx * 2;
            const float4 f0 = __ldg(src);
            const float4 f1 = __ldg(src + 1);
            __half2 hh[4];
            hh[0] = __floats2half2_rn(f0.x, f0.y);
            hh[1] = __floats2half2_rn(f0.z, f0.w);
            hh[2] = __floats2half2_rn(f1.x, f1.y);
            hh[3] = __floats2half2_rn(f1.z, f1.w);
            g_h16[idx] = *(const uint4*)hh;
        }
        return;
    }

    const int fb   = blockIdx.x - convBlocks;   // 0..31
    const int tid  = threadIdx.x;
    const int warp = tid >> 5;                  // 0..7
    const int lane = tid & 31;

    __shared__ float sW23c0[H1];
    __shared__ float sW23c1[H1];
    __shared__ float sTvec[H2];

    {   // W23 entry (k = tid>>1, c = tid&1): length-64 dot
        const int k = tid >> 1;
        const int c = tid & 1;
        const float* w2row = &W2[k * H2];
        float acc = 0.0f;
#pragma unroll 16
        for (int j = 0; j < H2; ++j)
            acc = fmaf(w2row[j], W3[j * 2 + c], acc);
        if (c == 0) sW23c0[k] = acc;
        else        sW23c1[k] = acc;
    }
    __syncthreads();

    {   // W_eff row 8*fb + warp
        const int row = fb * 8 + warp;
        const float4 a  = *(const float4*)&W1[row * H1 + 4 * lane];
        const float4 c0 = *(const float4*)&sW23c0[4 * lane];
        const float4 c1 = *(const float4*)&sW23c1[4 * lane];

        float s0, s1;
        s0 = a.x * c0.x;            s1 = a.x * c1.x;
        s0 = fmaf(a.y, c0.y, s0);   s1 = fmaf(a.y, c1.y, s1);
        s0 = fmaf(a.z, c0.z, s0);   s1 = fmaf(a.z, c1.z, s1);
        s0 = fmaf(a.w, c0.w, s0);   s1 = fmaf(a.w, c1.w, s1);
#pragma unroll
        for (int o = 16; o > 0; o >>= 1) {
            s0 += __shfl_xor_sync(0xffffffffu, s0, o);
            s1 += __shfl_xor_sync(0xffffffffu, s1, o);
        }
        if (lane == 0) {
            g_w[row]     = s0;
            g_w[D + row] = s1;
        }
    }

    if (fb == 0) {   // bias chain
#pragma unroll
        for (int jj = 0; jj < 8; ++jj) {
            const int j = warp * 8 + jj;
            float v =      b1[lane]      * W2[(lane)      * H2 + j];
            v = fmaf(b1[lane + 32],  W2[(lane + 32) * H2 + j], v);
            v = fmaf(b1[lane + 64],  W2[(lane + 64) * H2 + j], v);
            v = fmaf(b1[lane + 96],  W2[(lane + 96) * H2 + j], v);
#pragma unroll
            for (int o = 16; o > 0; o >>= 1)
                v += __shfl_xor_sync(0xffffffffu, v, o);
            if (lane == 0) sTvec[j] = v + b2[j];
        }
        __syncthreads();
        if (warp == 0) {
            float t0 = sTvec[lane], t1 = sTvec[lane + 32];
            float bb0 = fmaf(t0, W3[lane * 2 + 0], t1 * W3[(lane + 32) * 2 + 0]);
            float bb1 = fmaf(t0, W3[lane * 2 + 1], t1 * W3[(lane + 32) * 2 + 1]);
#pragma unroll
            for (int o = 16; o > 0; o >>= 1) {
                bb0 += __shfl_xor_sync(0xffffffffu, bb0, o);
                bb1 += __shfl_xor_sync(0xffffffffu, bb1, o);
            }
            if (lane == 0) {
                g_b[0] = bb0 + b3[0];
                g_b[1] = bb1 + b3[1];
            }
        }
    }
}

// Per-lane accumulate of one edge: acc0/acc1 += (x .* y) @ w
__device__ __forceinline__ void edge_accum(const uint4& xv, const uint4& yv,
                                           const unsigned long long* w0p,
                                           const unsigned long long* w1p,
                                           float& out0, float& out1) {
    const __half2* xh = (const __half2*)&xv;
    const __half2* yh = (const __half2*)&yv;
    unsigned long long A = 0ull, B = 0ull;
#pragma unroll
    for (int k = 0; k < 4; ++k) {
        const float2 pf = __half22float2(__hmul2(xh[k], yh[k]));
        unsigned long long pp;
        PACK_F32X2(pp, pf.x, pf.y);
        FMA_F32X2(A, pp, w0p[k], A);
        FMA_F32X2(B, pp, w1p[k], B);
    }
    float lo, hi;
    UNPACK_F32X2(lo, hi, A); out0 = lo + hi;
    UNPACK_F32X2(lo, hi, B); out1 = lo + hi;
}

// ---------------------------------------------------------------------------
// Main kernel: FOUR edges per warp-iteration. 8 gathers in flight; all 8
// logits reduced by a 3-level split butterfly (7 shfl + 7 add); lanes
// 0/8/16/24 finalize 4 softmaxes, stores coalesce into one 32 B segment.
// ---------------------------------------------------------------------------
__global__ void __launch_bounds__(256)
edge_predict_fp16(const int* __restrict__ edges,
                  float* __restrict__ out, int E) {
    const int  lane   = threadIdx.x & 31;
    const int  warp   = (blockIdx.x * blockDim.x + threadIdx.x) >> 5;
    const int  nwarps = (gridDim.x * blockDim.x) >> 5;
    const int  nQuads = E >> 2;
    const char* tbl   = (const char*)g_h16;
    const unsigned laneOff = (unsigned)lane << 4;

    // Per-lane weights packed as f32x2 pairs for channels 8l..8l+7.
    unsigned long long w0p[4], w1p[4];
#pragma unroll
    for (int k = 0; k < 4; ++k) {
        PACK_F32X2(w0p[k], g_w[8 * lane + 2 * k],     g_w[8 * lane + 2 * k + 1]);
        PACK_F32X2(w1p[k], g_w[D + 8 * lane + 2 * k], g_w[D + 8 * lane + 2 * k + 1]);
    }
    const float bias0 = g_b[0];
    const float bias1 = g_b[1];
    const bool hi16 = (lane & 16) != 0;
    const bool hi8  = (lane & 8)  != 0;
    const bool hi4  = (lane & 4)  != 0;

    for (int p = warp; p < nQuads; p += nwarps) {
        const int4 qa = __ldg((const int4*)edges + 2 * p);       // edges 4p, 4p+1
        const int4 qb = __ldg((const int4*)edges + 2 * p + 1);   // edges 4p+2, 4p+3

        // Issue all 8 gathers up-front (MLP = 8).
        const uint4 x0 = __ldg((const uint4*)(tbl + (((unsigned)qa.x << 9) + laneOff)));
        const uint4 y0 = __ldg((const uint4*)(tbl + (((unsigned)qa.y << 9) + laneOff)));
        const uint4 x1 = __ldg((const uint4*)(tbl + (((unsigned)qa.z << 9) + laneOff)));
        const uint4 y1 = __ldg((const uint4*)(tbl + (((unsigned)qa.w << 9) + laneOff)));
        const uint4 x2 = __ldg((const uint4*)(tbl + (((unsigned)qb.x << 9) + laneOff)));
        const uint4 y2 = __ldg((const uint4*)(tbl + (((unsigned)qb.y << 9) + laneOff)));
        const uint4 x3 = __ldg((const uint4*)(tbl + (((unsigned)qb.z << 9) + laneOff)));
        const uint4 y3 = __ldg((const uint4*)(tbl + (((unsigned)qb.w << 9) + laneOff)));

        float L00, L01, L10, L11, L20, L21, L30, L31;
        edge_accum(x0, y0, w0p, w1p, L00, L01);
        edge_accum(x1, y1, w0p, w1p, L10, L11);
        edge_accum(x2, y2, w0p, w1p, L20, L21);
        edge_accum(x3, y3, w0p, w1p, L30, L31);

        // ---- 3-level split butterfly over 8 logits ----
        // After xor16: low half owns edges {0,1}, high half edges {2,3}.
        float v0 = (hi16 ? L20 : L00) + __shfl_xor_sync(0xffffffffu, hi16 ? L00 : L20, 16);
        float v1 = (hi16 ? L21 : L01) + __shfl_xor_sync(0xffffffffu, hi16 ? L01 : L21, 16);
        float v2 = (hi16 ? L30 : L10) + __shfl_xor_sync(0xffffffffu, hi16 ? L10 : L30, 16);
        float v3 = (hi16 ? L31 : L11) + __shfl_xor_sync(0xffffffffu, hi16 ? L11 : L31, 16);
        // After xor8: bit3 selects edge within the pair.
        float w0 = (hi8 ? v2 : v0) + __shfl_xor_sync(0xffffffffu, hi8 ? v0 : v2, 8);
        float w1 = (hi8 ? v3 : v1) + __shfl_xor_sync(0xffffffffu, hi8 ? v1 : v3, 8);
        // After xor4: bit2 selects class.
        float u = (hi4 ? w1 : w0) + __shfl_xor_sync(0xffffffffu, hi4 ? w0 : w1, 4);
        // Shared butterflies within each 4-lane group.
        u += __shfl_xor_sync(0xffffffffu, u, 2);
        u += __shfl_xor_sync(0xffffffffu, u, 1);
        // Class partner lives 4 lanes away.
        const float uo = __shfl_xor_sync(0xffffffffu, u, 4);

        // Lanes 0,8,16,24 hold class-0 totals of edges 4p+(lane>>3).
        if ((lane & 7) == 0) {
            const float l0 = u  + bias0;
            const float l1 = uo + bias1;
            const float m  = fmaxf(l0, l1);
            const float e0 = expf(l0 - m);
            const float e1 = expf(l1 - m);
            const float inv = 1.0f / (e0 + e1);
            ((float2*)out)[4 * p + (lane >> 3)] = make_float2(e0 * inv, e1 * inv);
        }
    }

    // Tail for E not divisible by 4 (not hit for E = 1M).
    if (warp == 0) {
        for (int e = nQuads * 4 + (int)0; e < E; ++e) {
            const int2 st = __ldg((const int2*)edges + e);
            const uint4 xv = __ldg((const uint4*)(tbl + (((unsigned)st.x << 9) + laneOff)));
            const uint4 yv = __ldg((const uint4*)(tbl + (((unsigned)st.y << 9) + laneOff)));
            float a0, a1;
            edge_accum(xv, yv, w0p, w1p, a0, a1);
#pragma unroll
            for (int o = 16; o > 0; o >>= 1) {
                a0 += __shfl_xor_sync(0xffffffffu, a0, o);
                a1 += __shfl_xor_sync(0xffffffffu, a1, o);
            }
            if (lane == 0) {
                a0 += bias0; a1 += bias1;
                const float m  = fmaxf(a0, a1);
                const float e0 = expf(a0 - m);
                const float e1 = expf(a1 - m);
                const float inv = 1.0f / (e0 + e1);
                ((float2*)out)[e] = make_float2(e0 * inv, e1 * inv);
            }
        }
    }
}

extern "C" void kernel_launch(void* const* d_in, const int* in_sizes, int n_in,
                              void* d_out, int out_size) {
    const float* h     = (const float*)d_in[0];
    const int*   edges = (const int*)d_in[1];
    const float* W1    = (const float*)d_in[2];
    const float* b1    = (const float*)d_in[3];
    const float* W2    = (const float*)d_in[4];
    const float* b2    = (const float*)d_in[5];
    const float* W3    = (const float*)d_in[6];
    const float* b3    = (const float*)d_in[7];
    float*       out   = (float*)d_out;

    const int nElems = in_sizes[0];
    const int E      = in_sizes[1] / 2;

    const int convBlocks = (nElems / 8 + 255) / 256;   // 12500
    prep_kernel<<<convBlocks + 32, 256>>>(h, nElems, convBlocks,
                                          W1, W2, W3, b1, b2, b3);
    edge_predict_fp16<<<8880, 256>>>(edges, out, E);
}

// round 13
// speedup vs baseline: 1.5210x; 1.2116x over previous
#include <cuda_runtime.h>
#include <cuda_fp16.h>

#define D 256
#define H1 128
#define H2 64
#define N_NODES_MAX 100000

// Folded weights: g_w[0..255] = class-0 column of W1@W2@W3, g_w[256..511] = class 1.
__device__ float g_w[2 * D];
__device__ float g_b[2];
// fp16 copy of h: one row = 256 halves = 512 B = 32 uint4. 51.2 MB scratch.
__device__ uint4 g_h16[N_NODES_MAX * (D / 8)];

// ---------------------------------------------------------------------------
// Prep kernel (one launch):
//   blocks [0, convBlocks) : convert h (fp32) -> g_h16 (fp16)   [DRAM-floor]
//   blocks [convBlocks,+32): fold W_eff = W1@(W2@W3), b_eff     (fp32)
// ---------------------------------------------------------------------------
__global__ void __launch_bounds__(256)
prep_kernel(const float* __restrict__ h, int nElems, int convBlocks,
            const float* __restrict__ W1, const float* __restrict__ W2,
            const float* __restrict__ W3, const float* __restrict__ b1,
            const float* __restrict__ b2, const float* __restrict__ b3) {
    if (blockIdx.x < (unsigned)convBlocks) {
        const int idx  = blockIdx.x * 256 + threadIdx.x;
        const int base = idx * 8;
        if (base < nElems) {
            const float4* src = (const float4*)h + idx * 2;
            const float4 f0 = __ldg(src);
            const float4 f1 = __ldg(src + 1);
            __half2 hh[4];
            hh[0] = __floats2half2_rn(f0.x, f0.y);
            hh[1] = __floats2half2_rn(f0.z, f0.w);
            hh[2] = __floats2half2_rn(f1.x, f1.y);
            hh[3] = __floats2half2_rn(f1.z, f1.w);
            g_h16[idx] = *(const uint4*)hh;
        }
        return;
    }

    const int fb   = blockIdx.x - convBlocks;   // 0..31
    const int tid  = threadIdx.x;
    const int warp = tid >> 5;                  // 0..7
    const int lane = tid & 31;

    __shared__ float sW23c0[H1];
    __shared__ float sW23c1[H1];
    __shared__ float sTvec[H2];

    {   // W23 entry (k = tid>>1, c = tid&1): length-64 dot
        const int k = tid >> 1;
        const int c = tid & 1;
        const float* w2row = &W2[k * H2];
        float acc = 0.0f;
#pragma unroll 16
        for (int j = 0; j < H2; ++j)
            acc = fmaf(w2row[j], W3[j * 2 + c], acc);
        if (c == 0) sW23c0[k] = acc;
        else        sW23c1[k] = acc;
    }
    __syncthreads();

    {   // W_eff row 8*fb + warp
        const int row = fb * 8 + warp;
        const float4 a  = *(const float4*)&W1[row * H1 + 4 * lane];
        const float4 c0 = *(const float4*)&sW23c0[4 * lane];
        const float4 c1 = *(const float4*)&sW23c1[4 * lane];

        float s0, s1;
        s0 = a.x * c0.x;            s1 = a.x * c1.x;
        s0 = fmaf(a.y, c0.y, s0);   s1 = fmaf(a.y, c1.y, s1);
        s0 = fmaf(a.z, c0.z, s0);   s1 = fmaf(a.z, c1.z, s1);
        s0 = fmaf(a.w, c0.w, s0);   s1 = fmaf(a.w, c1.w, s1);
#pragma unroll
        for (int o = 16; o > 0; o >>= 1) {
            s0 += __shfl_xor_sync(0xffffffffu, s0, o);
            s1 += __shfl_xor_sync(0xffffffffu, s1, o);
        }
        if (lane == 0) {
            g_w[row]     = s0;
            g_w[D + row] = s1;
        }
    }

    if (fb == 0) {   // bias chain
#pragma unroll
        for (int jj = 0; jj < 8; ++jj) {
            const int j = warp * 8 + jj;
            float v =      b1[lane]      * W2[(lane)      * H2 + j];
            v = fmaf(b1[lane + 32],  W2[(lane + 32) * H2 + j], v);
            v = fmaf(b1[lane + 64],  W2[(lane + 64) * H2 + j], v);
            v = fmaf(b1[lane + 96],  W2[(lane + 96) * H2 + j], v);
#pragma unroll
            for (int o = 16; o > 0; o >>= 1)
                v += __shfl_xor_sync(0xffffffffu, v, o);
            if (lane == 0) sTvec[j] = v + b2[j];
        }
        __syncthreads();
        if (warp == 0) {
            float t0 = sTvec[lane], t1 = sTvec[lane + 32];
            float bb0 = fmaf(t0, W3[lane * 2 + 0], t1 * W3[(lane + 32) * 2 + 0]);
            float bb1 = fmaf(t0, W3[lane * 2 + 1], t1 * W3[(lane + 32) * 2 + 1]);
#pragma unroll
            for (int o = 16; o > 0; o >>= 1) {
                bb0 += __shfl_xor_sync(0xffffffffu, bb0, o);
                bb1 += __shfl_xor_sync(0xffffffffu, bb1, o);
            }
            if (lane == 0) {
                g_b[0] = bb0 + b3[0];
                g_b[1] = bb1 + b3[1];
            }
        }
    }
}

// Per-lane accumulate of one edge in fp16 (HMUL2 + HFMA2), fp32 final sum.
__device__ __forceinline__ void edge_accum_h(const uint4& xv, const uint4& yv,
                                             const __half2* w0h,
                                             const __half2* w1h,
                                             float& out0, float& out1) {
    const __half2* xh = (const __half2*)&xv;
    const __half2* yh = (const __half2*)&yv;
    __half2 a0 = __float2half2_rn(0.0f);
    __half2 a1 = __float2half2_rn(0.0f);
#pragma unroll
    for (int k = 0; k < 4; ++k) {
        const __half2 p = __hmul2(xh[k], yh[k]);
        a0 = __hfma2(p, w0h[k], a0);
        a1 = __hfma2(p, w1h[k], a1);
    }
    const float2 f0 = __half22float2(a0);
    const float2 f1 = __half22float2(a1);
    out0 = f0.x + f0.y;
    out1 = f1.x + f1.y;
}

// ---------------------------------------------------------------------------
// Main kernel: FOUR edges per warp-iteration, fp16 weights + HFMA2 math.
// __launch_bounds__(256, 6) pins regs <= 42 -> 6 CTAs/SM (~75% occ).
// All 8 logits reduced by a 3-level split butterfly; lanes 0/8/16/24
// finalize 4 softmaxes; stores coalesce into one 32 B segment.
// ---------------------------------------------------------------------------
__global__ void __launch_bounds__(256, 6)
edge_predict_fp16(const int* __restrict__ edges,
                  float* __restrict__ out, int E) {
    const int  lane   = threadIdx.x & 31;
    const int  warp   = (blockIdx.x * blockDim.x + threadIdx.x) >> 5;
    const int  nwarps = (gridDim.x * blockDim.x) >> 5;
    const int  nQuads = E >> 2;
    const char* tbl   = (const char*)g_h16;
    const unsigned laneOff = (unsigned)lane << 4;

    // Per-lane fp16 weights for channels 8l..8l+7, packed as half2 pairs.
    __half2 w0h[4], w1h[4];
#pragma unroll
    for (int k = 0; k < 4; ++k) {
        w0h[k] = __floats2half2_rn(g_w[8 * lane + 2 * k],     g_w[8 * lane + 2 * k + 1]);
        w1h[k] = __floats2half2_rn(g_w[D + 8 * lane + 2 * k], g_w[D + 8 * lane + 2 * k + 1]);
    }
    const float bias0 = g_b[0];
    const float bias1 = g_b[1];
    const bool hi16 = (lane & 16) != 0;
    const bool hi8  = (lane & 8)  != 0;
    const bool hi4  = (lane & 4)  != 0;

    for (int p = warp; p < nQuads; p += nwarps) {
        const int4 qa = __ldg((const int4*)edges + 2 * p);       // edges 4p, 4p+1
        const int4 qb = __ldg((const int4*)edges + 2 * p + 1);   // edges 4p+2, 4p+3

        // Issue all 8 gathers up-front (MLP = 8).
        const uint4 x0 = __ldg((const uint4*)(tbl + (((unsigned)qa.x << 9) + laneOff)));
        const uint4 y0 = __ldg((const uint4*)(tbl + (((unsigned)qa.y << 9) + laneOff)));
        const uint4 x1 = __ldg((const uint4*)(tbl + (((unsigned)qa.z << 9) + laneOff)));
        const uint4 y1 = __ldg((const uint4*)(tbl + (((unsigned)qa.w << 9) + laneOff)));
        const uint4 x2 = __ldg((const uint4*)(tbl + (((unsigned)qb.x << 9) + laneOff)));
        const uint4 y2 = __ldg((const uint4*)(tbl + (((unsigned)qb.y << 9) + laneOff)));
        const uint4 x3 = __ldg((const uint4*)(tbl + (((unsigned)qb.z << 9) + laneOff)));
        const uint4 y3 = __ldg((const uint4*)(tbl + (((unsigned)qb.w << 9) + laneOff)));

        float L00, L01, L10, L11, L20, L21, L30, L31;
        edge_accum_h(x0, y0, w0h, w1h, L00, L01);
        edge_accum_h(x1, y1, w0h, w1h, L10, L11);
        edge_accum_h(x2, y2, w0h, w1h, L20, L21);
        edge_accum_h(x3, y3, w0h, w1h, L30, L31);

        // ---- 3-level split butterfly over 8 logits (fp32) ----
        float v0 = (hi16 ? L20 : L00) + __shfl_xor_sync(0xffffffffu, hi16 ? L00 : L20, 16);
        float v1 = (hi16 ? L21 : L01) + __shfl_xor_sync(0xffffffffu, hi16 ? L01 : L21, 16);
        float v2 = (hi16 ? L30 : L10) + __shfl_xor_sync(0xffffffffu, hi16 ? L10 : L30, 16);
        float v3 = (hi16 ? L31 : L11) + __shfl_xor_sync(0xffffffffu, hi16 ? L11 : L31, 16);
        float w0 = (hi8 ? v2 : v0) + __shfl_xor_sync(0xffffffffu, hi8 ? v0 : v2, 8);
        float w1 = (hi8 ? v3 : v1) + __shfl_xor_sync(0xffffffffu, hi8 ? v1 : v3, 8);
        float u  = (hi4 ? w1 : w0) + __shfl_xor_sync(0xffffffffu, hi4 ? w0 : w1, 4);
        u += __shfl_xor_sync(0xffffffffu, u, 2);
        u += __shfl_xor_sync(0xffffffffu, u, 1);
        const float uo = __shfl_xor_sync(0xffffffffu, u, 4);

        // Lanes 0,8,16,24 hold class-0 totals of edges 4p+(lane>>3).
        if ((lane & 7) == 0) {
            const float l0 = u  + bias0;
            const float l1 = uo + bias1;
            const float m  = fmaxf(l0, l1);
            const float e0 = expf(l0 - m);
            const float e1 = expf(l1 - m);
            const float inv = 1.0f / (e0 + e1);
            ((float2*)out)[4 * p + (lane >> 3)] = make_float2(e0 * inv, e1 * inv);
        }
    }

    // Tail for E not divisible by 4 (not hit for E = 1M).
    if (warp == 0) {
        for (int e = nQuads * 4; e < E; ++e) {
            const int2 st = __ldg((const int2*)edges + e);
            const uint4 xv = __ldg((const uint4*)(tbl + (((unsigned)st.x << 9) + laneOff)));
            const uint4 yv = __ldg((const uint4*)(tbl + (((unsigned)st.y << 9) + laneOff)));
            float a0, a1;
            edge_accum_h(xv, yv, w0h, w1h, a0, a1);
#pragma unroll
            for (int o = 16; o > 0; o >>= 1) {
                a0 += __shfl_xor_sync(0xffffffffu, a0, o);
                a1 += __shfl_xor_sync(0xffffffffu, a1, o);
            }
            if (lane == 0) {
                a0 += bias0; a1 += bias1;
                const float m  = fmaxf(a0, a1);
                const float e0 = expf(a0 - m);
                const float e1 = expf(a1 - m);
                const float inv = 1.0f / (e0 + e1);
                ((float2*)out)[e] = make_float2(e0 * inv, e1 * inv);
            }
        }
    }
}

extern "C" void kernel_launch(void* const* d_in, const int* in_sizes, int n_in,
                              void* d_out, int out_size) {
    const float* h     = (const float*)d_in[0];
    const int*   edges = (const int*)d_in[1];
    const float* W1    = (const float*)d_in[2];
    const float* b1    = (const float*)d_in[3];
    const float* W2    = (const float*)d_in[4];
    const float* b2    = (const float*)d_in[5];
    const float* W3    = (const float*)d_in[6];
    const float* b3    = (const float*)d_in[7];
    float*       out   = (float*)d_out;

    const int nElems = in_sizes[0];
    const int E      = in_sizes[1] / 2;

    const int convBlocks = (nElems / 8 + 255) / 256;   // 12500
    prep_kernel<<<convBlocks + 32, 256>>>(h, nElems, convBlocks,
                                          W1, W2, W3, b1, b2, b3);
    edge_predict_fp16<<<8880, 256>>>(edges, out, E);
}